// round 1
// baseline (speedup 1.0000x reference)
#include <cuda_runtime.h>

// Problem shape (fixed by the dataset)
#define S_LEN   2048
#define D_MODEL 1024
#define NHEAD   16
#define HDIM    64
#define BATCH   2
#define MTOT    (BATCH * S_LEN)   // 4096

// Scratch (allocation-free rule: __device__ globals)
__device__ float g_q[(size_t)BATCH * NHEAD * S_LEN * HDIM];
__device__ float g_k[(size_t)BATCH * NHEAD * S_LEN * HDIM];
__device__ float g_v[(size_t)BATCH * NHEAD * S_LEN * HDIM];
__device__ float g_vals[(size_t)MTOT * D_MODEL];

// ---------------------------------------------------------------------------
// GEMM 1: qkv = x @ w_qkv^T + b_qkv, scattered into g_q/g_k/g_v [B,H,S,hd]
// C[m][n], m = b*2048+s, n -> h = n/192, part = (n%192)/64, d = n%64
// Tiles: BM=BN=128, BK=16, 256 threads, 8x8 micro-tile, stride-16 mapping.
// ---------------------------------------------------------------------------
__global__ __launch_bounds__(256) void gemm_qkv_kernel(
    const float* __restrict__ X, const float* __restrict__ W,
    const float* __restrict__ bias)
{
    __shared__ float As[128 * 17];
    __shared__ float Bs[128 * 17];
    const int K = D_MODEL;
    const int t  = threadIdx.x;
    const int tx = t & 15, ty = t >> 4;
    const int m0 = blockIdx.y * 128;
    const int n0 = blockIdx.x * 128;

    float acc[8][8];
#pragma unroll
    for (int i = 0; i < 8; i++)
#pragma unroll
        for (int j = 0; j < 8; j++) acc[i][j] = 0.0f;

    for (int k0 = 0; k0 < K; k0 += 16) {
#pragma unroll
        for (int it = 0; it < 2; it++) {
            int idx = t + it * 256;
            int row = idx >> 2;
            int c4  = (idx & 3) << 2;
            float4 fa = *reinterpret_cast<const float4*>(X + (size_t)(m0 + row) * K + k0 + c4);
            As[row * 17 + c4 + 0] = fa.x;
            As[row * 17 + c4 + 1] = fa.y;
            As[row * 17 + c4 + 2] = fa.z;
            As[row * 17 + c4 + 3] = fa.w;
            float4 fb = *reinterpret_cast<const float4*>(W + (size_t)(n0 + row) * K + k0 + c4);
            Bs[row * 17 + c4 + 0] = fb.x;
            Bs[row * 17 + c4 + 1] = fb.y;
            Bs[row * 17 + c4 + 2] = fb.z;
            Bs[row * 17 + c4 + 3] = fb.w;
        }
        __syncthreads();
#pragma unroll
        for (int kk = 0; kk < 16; kk++) {
            float a[8], b[8];
#pragma unroll
            for (int i = 0; i < 8; i++) a[i] = As[(ty + 16 * i) * 17 + kk];
#pragma unroll
            for (int j = 0; j < 8; j++) b[j] = Bs[(tx + 16 * j) * 17 + kk];
#pragma unroll
            for (int i = 0; i < 8; i++)
#pragma unroll
                for (int j = 0; j < 8; j++) acc[i][j] = fmaf(a[i], b[j], acc[i][j]);
        }
        __syncthreads();
    }

#pragma unroll
    for (int j = 0; j < 8; j++) {
        int n = n0 + tx + 16 * j;
        float bn = bias[n];
        int h = n / 192;
        int r = n - h * 192;
        int part = r >> 6;
        int d = r & 63;
#pragma unroll
        for (int i = 0; i < 8; i++) {
            int m  = m0 + ty + 16 * i;
            int bb = m >> 11;
            int s  = m & 2047;
            size_t off = (((size_t)bb * NHEAD + h) * S_LEN + s) * HDIM + d;
            float v = acc[i][j] + bn;
            if (part == 0)      g_q[off] = v;
            else if (part == 1) g_k[off] = v;
            else                g_v[off] = v;
        }
    }
}

// ---------------------------------------------------------------------------
// Flash attention, fp32. One block = 128 q rows of one (b,h).
// 256 threads; thread (ty,tx) owns q rows {ty+16i, i<8}, k/d cols {tx+16j, j<4}.
// K stored transposed in smem (KT[d][k], pad 65) -> conflict-free score reads.
// ---------------------------------------------------------------------------
#define ATTN_SMEM_FLOATS (65 * (128 + 64 + 64 + 128))

__global__ __launch_bounds__(256) void attn_kernel()
{
    extern __shared__ float sm[];
    float* Qs = sm;                       // [128][65]
    float* KT = Qs + 128 * 65;            // [64][65]  (KT[d][k])
    float* Vs = KT + 64 * 65;             // [64][65]  (Vs[k][d])
    float* Ps = Vs + 64 * 65;             // [128][65]

    const int t  = threadIdx.x;
    const int tx = t & 15, ty = t >> 4;
    const int q0 = blockIdx.x * 128;
    const int h  = blockIdx.y;
    const int bz = blockIdx.z;
    const size_t headoff = ((size_t)bz * NHEAD + h) * S_LEN * HDIM;

    // Load Q tile: 128x64 floats
#pragma unroll
    for (int it = 0; it < 8; it++) {
        int idx = t + it * 256;
        int qr  = idx >> 4;
        int dv  = (idx & 15) << 2;
        float4 f = *reinterpret_cast<const float4*>(g_q + headoff + (size_t)(q0 + qr) * HDIM + dv);
        Qs[qr * 65 + dv + 0] = f.x;
        Qs[qr * 65 + dv + 1] = f.y;
        Qs[qr * 65 + dv + 2] = f.z;
        Qs[qr * 65 + dv + 3] = f.w;
    }
    __syncthreads();

    float acc[8][4];
    float mrow[8], lrow[8];
#pragma unroll
    for (int i = 0; i < 8; i++) {
        mrow[i] = -1e30f;
        lrow[i] = 0.0f;
#pragma unroll
        for (int j = 0; j < 4; j++) acc[i][j] = 0.0f;
    }

    for (int kt = 0; kt < S_LEN; kt += 64) {
        // Load K (transposed) and V tiles
#pragma unroll
        for (int it = 0; it < 4; it++) {
            int idx = t + it * 256;
            int kr  = idx >> 4;
            int dv  = (idx & 15) << 2;
            size_t goff = headoff + (size_t)(kt + kr) * HDIM + dv;
            float4 fk = *reinterpret_cast<const float4*>(g_k + goff);
            KT[(dv + 0) * 65 + kr] = fk.x;
            KT[(dv + 1) * 65 + kr] = fk.y;
            KT[(dv + 2) * 65 + kr] = fk.z;
            KT[(dv + 3) * 65 + kr] = fk.w;
            float4 fv = *reinterpret_cast<const float4*>(g_v + goff);
            Vs[kr * 65 + dv + 0] = fv.x;
            Vs[kr * 65 + dv + 1] = fv.y;
            Vs[kr * 65 + dv + 2] = fv.z;
            Vs[kr * 65 + dv + 3] = fv.w;
        }
        __syncthreads();

        // Scores: s[i][j] = sum_d Q[qr_i][d] * K[kc_j][d]
        float s[8][4];
#pragma unroll
        for (int i = 0; i < 8; i++)
#pragma unroll
            for (int j = 0; j < 4; j++) s[i][j] = 0.0f;

#pragma unroll 4
        for (int d = 0; d < HDIM; d++) {
            float a[8], b[4];
#pragma unroll
            for (int i = 0; i < 8; i++) a[i] = Qs[(ty + 16 * i) * 65 + d];
#pragma unroll
            for (int j = 0; j < 4; j++) b[j] = KT[d * 65 + tx + 16 * j];
#pragma unroll
            for (int i = 0; i < 8; i++)
#pragma unroll
                for (int j = 0; j < 4; j++) s[i][j] = fmaf(a[i], b[j], s[i][j]);
        }

        // Online softmax (scale = 1/sqrt(64) = 0.125)
#pragma unroll
        for (int i = 0; i < 8; i++) {
            float mloc = -1e30f;
#pragma unroll
            for (int j = 0; j < 4; j++) {
                s[i][j] *= 0.125f;
                mloc = fmaxf(mloc, s[i][j]);
            }
#pragma unroll
            for (int off = 8; off >= 1; off >>= 1)
                mloc = fmaxf(mloc, __shfl_xor_sync(0xffffffffu, mloc, off, 16));
            float mnew = fmaxf(mrow[i], mloc);
            float corr = __expf(mrow[i] - mnew);
            mrow[i] = mnew;
            float ls = 0.0f;
#pragma unroll
            for (int j = 0; j < 4; j++) {
                float p = __expf(s[i][j] - mnew);
                s[i][j] = p;
                ls += p;
            }
#pragma unroll
            for (int off = 8; off >= 1; off >>= 1)
                ls += __shfl_xor_sync(0xffffffffu, ls, off, 16);
            lrow[i] = lrow[i] * corr + ls;
#pragma unroll
            for (int j = 0; j < 4; j++) acc[i][j] *= corr;
#pragma unroll
            for (int j = 0; j < 4; j++) Ps[(ty + 16 * i) * 65 + tx + 16 * j] = s[i][j];
        }
        __syncthreads();

        // O += P @ V
#pragma unroll 4
        for (int k = 0; k < 64; k++) {
            float a[8], b[4];
#pragma unroll
            for (int i = 0; i < 8; i++) a[i] = Ps[(ty + 16 * i) * 65 + k];
#pragma unroll
            for (int j = 0; j < 4; j++) b[j] = Vs[k * 65 + tx + 16 * j];
#pragma unroll
            for (int i = 0; i < 8; i++)
#pragma unroll
                for (int j = 0; j < 4; j++) acc[i][j] = fmaf(a[i], b[j], acc[i][j]);
        }
        __syncthreads();
    }

    // Normalize and write to g_vals[B,S,D] with col = h*64 + d
#pragma unroll
    for (int i = 0; i < 8; i++) {
        float inv = 1.0f / lrow[i];
        int row = q0 + ty + 16 * i;
#pragma unroll
        for (int j = 0; j < 4; j++) {
            int col = h * HDIM + tx + 16 * j;
            g_vals[((size_t)bz * S_LEN + row) * D_MODEL + col] = acc[i][j] * inv;
        }
    }
}

// ---------------------------------------------------------------------------
// GEMM 2: out = vals @ w_o^T + b_o   (M=4096, N=1024, K=1024)
// ---------------------------------------------------------------------------
__global__ __launch_bounds__(256) void gemm_o_kernel(
    const float* __restrict__ W, const float* __restrict__ bias,
    float* __restrict__ out)
{
    __shared__ float As[128 * 17];
    __shared__ float Bs[128 * 17];
    const int K = D_MODEL;
    const int t  = threadIdx.x;
    const int tx = t & 15, ty = t >> 4;
    const int m0 = blockIdx.y * 128;
    const int n0 = blockIdx.x * 128;

    float acc[8][8];
#pragma unroll
    for (int i = 0; i < 8; i++)
#pragma unroll
        for (int j = 0; j < 8; j++) acc[i][j] = 0.0f;

    for (int k0 = 0; k0 < K; k0 += 16) {
#pragma unroll
        for (int it = 0; it < 2; it++) {
            int idx = t + it * 256;
            int row = idx >> 2;
            int c4  = (idx & 3) << 2;
            float4 fa = *reinterpret_cast<const float4*>(g_vals + (size_t)(m0 + row) * K + k0 + c4);
            As[row * 17 + c4 + 0] = fa.x;
            As[row * 17 + c4 + 1] = fa.y;
            As[row * 17 + c4 + 2] = fa.z;
            As[row * 17 + c4 + 3] = fa.w;
            float4 fb = *reinterpret_cast<const float4*>(W + (size_t)(n0 + row) * K + k0 + c4);
            Bs[row * 17 + c4 + 0] = fb.x;
            Bs[row * 17 + c4 + 1] = fb.y;
            Bs[row * 17 + c4 + 2] = fb.z;
            Bs[row * 17 + c4 + 3] = fb.w;
        }
        __syncthreads();
#pragma unroll
        for (int kk = 0; kk < 16; kk++) {
            float a[8], b[8];
#pragma unroll
            for (int i = 0; i < 8; i++) a[i] = As[(ty + 16 * i) * 17 + kk];
#pragma unroll
            for (int j = 0; j < 8; j++) b[j] = Bs[(tx + 16 * j) * 17 + kk];
#pragma unroll
            for (int i = 0; i < 8; i++)
#pragma unroll
                for (int j = 0; j < 8; j++) acc[i][j] = fmaf(a[i], b[j], acc[i][j]);
        }
        __syncthreads();
    }

#pragma unroll
    for (int j = 0; j < 8; j++) {
        int n = n0 + tx + 16 * j;
        float bn = bias[n];
#pragma unroll
        for (int i = 0; i < 8; i++) {
            int m = m0 + ty + 16 * i;
            out[(size_t)m * D_MODEL + n] = acc[i][j] + bn;
        }
    }
}

// ---------------------------------------------------------------------------
// Launch
// ---------------------------------------------------------------------------
extern "C" void kernel_launch(void* const* d_in, const int* in_sizes, int n_in,
                              void* d_out, int out_size)
{
    const float* x     = (const float*)d_in[0];
    const float* w_qkv = (const float*)d_in[1];
    const float* b_qkv = (const float*)d_in[2];
    const float* w_o   = (const float*)d_in[3];
    const float* b_o   = (const float*)d_in[4];
    float* out = (float*)d_out;

    // QKV projection: N=3072 -> 24 tiles, M=4096 -> 32 tiles
    gemm_qkv_kernel<<<dim3(24, 32), 256>>>(x, w_qkv, b_qkv);

    // Attention: 16 q-tiles x 16 heads x 2 batches
    const int attn_smem = ATTN_SMEM_FLOATS * (int)sizeof(float);  // 99840 B
    cudaFuncSetAttribute(attn_kernel, cudaFuncAttributeMaxDynamicSharedMemorySize, attn_smem);
    attn_kernel<<<dim3(S_LEN / 128, NHEAD, BATCH), 256, attn_smem>>>();

    // Output projection: N=1024 -> 8 tiles, M=4096 -> 32 tiles
    gemm_o_kernel<<<dim3(8, 32), 256>>>(w_o, b_o, out);
}

// round 3
// speedup vs baseline: 3.4287x; 3.4287x over previous
#include <cuda_runtime.h>

#define S_LEN   2048
#define D_MODEL 1024
#define NHEAD   16
#define HDIM    64
#define BATCH   2

// Scratch (allocation-free rule: __device__ globals)
__device__ float g_q[(size_t)BATCH * NHEAD * S_LEN * HDIM];
__device__ float g_k[(size_t)BATCH * NHEAD * S_LEN * HDIM];
__device__ float g_v[(size_t)BATCH * NHEAD * S_LEN * HDIM];
__device__ float g_vals[(size_t)BATCH * S_LEN * D_MODEL];

// ---------------------------------------------------------------------------
// Helpers: tf32 mma (m16n8k8), fp32->tf32 RNA convert, cp.async
// ---------------------------------------------------------------------------
__device__ __forceinline__ unsigned f2tf(float x) {
    unsigned r; asm("cvt.rna.tf32.f32 %0, %1;" : "=r"(r) : "f"(x)); return r;
}
__device__ __forceinline__ void mma8(float* d, const unsigned* a, const unsigned* b) {
    asm volatile("mma.sync.aligned.m16n8k8.row.col.f32.tf32.tf32.f32 "
        "{%0,%1,%2,%3}, {%4,%5,%6,%7}, {%8,%9}, {%0,%1,%2,%3};"
        : "+f"(d[0]), "+f"(d[1]), "+f"(d[2]), "+f"(d[3])
        : "r"(a[0]), "r"(a[1]), "r"(a[2]), "r"(a[3]), "r"(b[0]), "r"(b[1]));
}
__device__ __forceinline__ void cp16(unsigned dst, const float* src) {
    asm volatile("cp.async.cg.shared.global [%0], [%1], 16;" :: "r"(dst), "l"(src) : "memory");
}
#define CP_COMMIT asm volatile("cp.async.commit_group;" ::: "memory")
#define CP_WAIT1  asm volatile("cp.async.wait_group 1;" ::: "memory")
#define CP_WAIT0  asm volatile("cp.async.wait_group 0;" ::: "memory")

// ---------------------------------------------------------------------------
// Shared GEMM core: C(128x128) = A(128xK) * B(128xK)^T, tf32 tensor cores.
// 256 threads, 8 warps in 2x4 grid, warp tile 64x32, BK=32, 2-stage cp.async.
// smem stride 36 floats -> all fragment loads are bank-conflict-free.
// ---------------------------------------------------------------------------
#define GSTR 36
#define GSZ  (128*GSTR)

__device__ __forceinline__ void gemm_tc_core(
    const float* __restrict__ A, const float* __restrict__ B, int K,
    int m0, int n0, float acc[4][4][4], float* sm)
{
    float* As = sm;            // [2][GSZ]
    float* Bs = sm + 2 * GSZ;  // [2][GSZ]
    unsigned sA = (unsigned)__cvta_generic_to_shared(As);
    unsigned sB = (unsigned)__cvta_generic_to_shared(Bs);
    const int t = threadIdx.x;
    const int lane = t & 31, w = t >> 5;
    const int g = lane >> 2, cc = lane & 3;
    const int wm = w >> 2, wn = w & 3;

#pragma unroll
    for (int mt = 0; mt < 4; mt++)
#pragma unroll
        for (int nt = 0; nt < 4; nt++)
#pragma unroll
            for (int j = 0; j < 4; j++) acc[mt][nt][j] = 0.0f;

    auto issue = [&](int it, int st) {
        int k0 = it * 32;
#pragma unroll
        for (int i = 0; i < 4; i++) {
            int chunk = t + i * 256;            // 0..1023
            int row = chunk >> 3, c4 = (chunk & 7) << 2;
            cp16(sA + (unsigned)(st * GSZ + row * GSTR + c4) * 4u,
                 A + (size_t)(m0 + row) * K + k0 + c4);
            cp16(sB + (unsigned)(st * GSZ + row * GSTR + c4) * 4u,
                 B + (size_t)(n0 + row) * K + k0 + c4);
        }
    };

    const int NIT = K / 32;
    issue(0, 0); CP_COMMIT;
    for (int it = 0; it < NIT; it++) {
        int st = it & 1;
        if (it + 1 < NIT) { issue(it + 1, st ^ 1); CP_COMMIT; CP_WAIT1; }
        else { CP_WAIT0; }
        __syncthreads();
        const float* as = As + st * GSZ;
        const float* bs = Bs + st * GSZ;
#pragma unroll
        for (int kk = 0; kk < 32; kk += 8) {
            unsigned af[4][4], bf[4][2];
#pragma unroll
            for (int mt = 0; mt < 4; mt++) {
                int r = 64 * wm + 16 * mt + g;
                af[mt][0] = f2tf(as[r * GSTR + kk + cc]);
                af[mt][1] = f2tf(as[(r + 8) * GSTR + kk + cc]);
                af[mt][2] = f2tf(as[r * GSTR + kk + cc + 4]);
                af[mt][3] = f2tf(as[(r + 8) * GSTR + kk + cc + 4]);
            }
#pragma unroll
            for (int nt = 0; nt < 4; nt++) {
                int col = 32 * wn + 8 * nt + g;
                bf[nt][0] = f2tf(bs[col * GSTR + kk + cc]);
                bf[nt][1] = f2tf(bs[col * GSTR + kk + cc + 4]);
            }
#pragma unroll
            for (int mt = 0; mt < 4; mt++)
#pragma unroll
                for (int nt = 0; nt < 4; nt++)
                    mma8(acc[mt][nt], af[mt], bf[nt]);
        }
        __syncthreads();
    }
}

// ---------------------------------------------------------------------------
// GEMM 1: qkv = x @ w_qkv^T + b_qkv, scattered into g_q/g_k/g_v [B,H,S,hd]
// ---------------------------------------------------------------------------
__global__ __launch_bounds__(256) void gemm_qkv_tc(
    const float* __restrict__ X, const float* __restrict__ W,
    const float* __restrict__ bias)
{
    extern __shared__ float sm[];
    float acc[4][4][4];
    const int m0 = blockIdx.y * 128, n0 = blockIdx.x * 128;
    gemm_tc_core(X, W, D_MODEL, m0, n0, acc, sm);

    const int lane = threadIdx.x & 31, w = threadIdx.x >> 5;
    const int g = lane >> 2, cc = lane & 3;
    const int wm = w >> 2, wn = w & 3;
#pragma unroll
    for (int mt = 0; mt < 4; mt++) {
#pragma unroll
        for (int nt = 0; nt < 4; nt++) {
            int n = n0 + 32 * wn + 8 * nt + 2 * cc;
            int h = n / 192;
            int r = n - h * 192;
            int part = r >> 6;
            int d = r & 63;
            float* dst = (part == 0) ? g_q : (part == 1) ? g_k : g_v;
            float b0 = bias[n], b1 = bias[n + 1];
#pragma unroll
            for (int hi = 0; hi < 2; hi++) {
                int m = m0 + 64 * wm + 16 * mt + g + 8 * hi;
                int bb = m >> 11, s = m & 2047;
                size_t off = (((size_t)bb * NHEAD + h) * S_LEN + s) * HDIM + d;
                *reinterpret_cast<float2*>(dst + off) =
                    make_float2(acc[mt][nt][2 * hi] + b0, acc[mt][nt][2 * hi + 1] + b1);
            }
        }
    }
}

// ---------------------------------------------------------------------------
// GEMM 2: out = vals @ w_o^T + b_o
// ---------------------------------------------------------------------------
__global__ __launch_bounds__(256) void gemm_o_tc(
    const float* __restrict__ W, const float* __restrict__ bias,
    float* __restrict__ out)
{
    extern __shared__ float sm[];
    float acc[4][4][4];
    const int m0 = blockIdx.y * 128, n0 = blockIdx.x * 128;
    gemm_tc_core(g_vals, W, D_MODEL, m0, n0, acc, sm);

    const int lane = threadIdx.x & 31, w = threadIdx.x >> 5;
    const int g = lane >> 2, cc = lane & 3;
    const int wm = w >> 2, wn = w & 3;
#pragma unroll
    for (int mt = 0; mt < 4; mt++) {
#pragma unroll
        for (int nt = 0; nt < 4; nt++) {
            int n = n0 + 32 * wn + 8 * nt + 2 * cc;
            float b0 = bias[n], b1 = bias[n + 1];
#pragma unroll
            for (int hi = 0; hi < 2; hi++) {
                int m = m0 + 64 * wm + 16 * mt + g + 8 * hi;
                *reinterpret_cast<float2*>(out + (size_t)m * D_MODEL + n) =
                    make_float2(acc[mt][nt][2 * hi] + b0, acc[mt][nt][2 * hi + 1] + b1);
            }
        }
    }
}

// ---------------------------------------------------------------------------
// Flash attention with tf32 mma. One block = 128 q rows of one (b,h).
// 8 warps, each owns 16 q rows. Q frags in registers (pre-scaled by 0.125).
// K/V tiles (64 x 64) double-buffered via cp.async. P staged through per-warp
// smem as pre-converted tf32. All fragment LDS patterns bank-conflict-free.
// ---------------------------------------------------------------------------
#define KSTR 68
#define VSTR 72
#define PSTR 68
#define ATTN_SMEM_FLOATS (128*PSTR + 2*64*KSTR + 2*64*VSTR)   // 26624

__global__ __launch_bounds__(256) void attn_tc()
{
    extern __shared__ float sm[];
    float* Ps = sm;                          // [128][PSTR] (tf32 bits)
    float* Ks = sm + 128 * PSTR;             // [2][64][KSTR]
    float* Vs = Ks + 2 * 64 * KSTR;          // [2][64][VSTR]
    unsigned* Pu = (unsigned*)Ps;
    unsigned sK = (unsigned)__cvta_generic_to_shared(Ks);
    unsigned sV = (unsigned)__cvta_generic_to_shared(Vs);

    const int t = threadIdx.x, lane = t & 31, w = t >> 5;
    const int g = lane >> 2, cc = lane & 3;
    const int q0 = blockIdx.x * 128;
    const size_t base = (((size_t)blockIdx.z * NHEAD + blockIdx.y) * S_LEN) * HDIM;

    // Q fragments, scaled by 1/sqrt(64) = 0.125 (exact power of 2)
    unsigned qf[8][4];
    const int r0 = q0 + 16 * w + g;
    const float* Qg = g_q + base;
#pragma unroll
    for (int ks = 0; ks < 8; ks++) {
        int col = 8 * ks + cc;
        qf[ks][0] = f2tf(0.125f * Qg[(size_t)r0 * HDIM + col]);
        qf[ks][1] = f2tf(0.125f * Qg[(size_t)(r0 + 8) * HDIM + col]);
        qf[ks][2] = f2tf(0.125f * Qg[(size_t)r0 * HDIM + col + 4]);
        qf[ks][3] = f2tf(0.125f * Qg[(size_t)(r0 + 8) * HDIM + col + 4]);
    }

    float o[8][4];
#pragma unroll
    for (int nt = 0; nt < 8; nt++)
#pragma unroll
        for (int j = 0; j < 4; j++) o[nt][j] = 0.0f;
    float mr0 = -1e30f, mr1 = -1e30f, lr0 = 0.0f, lr1 = 0.0f;

    auto issue = [&](int kt, int st) {
        const float* kg = g_k + base + (size_t)kt * 64 * HDIM;
        const float* vg = g_v + base + (size_t)kt * 64 * HDIM;
#pragma unroll
        for (int i = 0; i < 4; i++) {
            int chunk = t + i * 256;            // 0..1023
            int row = chunk >> 4, c4 = (chunk & 15) << 2;
            cp16(sK + (unsigned)(st * 64 * KSTR + row * KSTR + c4) * 4u, kg + row * HDIM + c4);
            cp16(sV + (unsigned)(st * 64 * VSTR + row * VSTR + c4) * 4u, vg + row * HDIM + c4);
        }
    };

    const int NT = S_LEN / 64;
    issue(0, 0); CP_COMMIT;
    for (int kt = 0; kt < NT; kt++) {
        int st = kt & 1;
        if (kt + 1 < NT) { issue(kt + 1, st ^ 1); CP_COMMIT; CP_WAIT1; }
        else { CP_WAIT0; }
        __syncthreads();

        const float* kp = Ks + st * 64 * KSTR;
        const float* vp = Vs + st * 64 * VSTR;

        // Scores: S = (Q*0.125) @ K^T  (128 x 64), warp owns 16 rows
        float s[8][4];
#pragma unroll
        for (int nt = 0; nt < 8; nt++)
#pragma unroll
            for (int j = 0; j < 4; j++) s[nt][j] = 0.0f;
#pragma unroll
        for (int ks = 0; ks < 8; ks++) {
#pragma unroll
            for (int nt = 0; nt < 8; nt++) {
                unsigned bf[2];
                int kv = 8 * nt + g;
                bf[0] = f2tf(kp[kv * KSTR + 8 * ks + cc]);
                bf[1] = f2tf(kp[kv * KSTR + 8 * ks + cc + 4]);
                mma8(s[nt], qf[ks], bf);
            }
        }

        // Online softmax on C-fragments (rows g and g+8, quad = 4 lanes)
        float mx0 = -1e30f, mx1 = -1e30f;
#pragma unroll
        for (int nt = 0; nt < 8; nt++) {
            mx0 = fmaxf(mx0, fmaxf(s[nt][0], s[nt][1]));
            mx1 = fmaxf(mx1, fmaxf(s[nt][2], s[nt][3]));
        }
        mx0 = fmaxf(mx0, __shfl_xor_sync(0xffffffffu, mx0, 1));
        mx0 = fmaxf(mx0, __shfl_xor_sync(0xffffffffu, mx0, 2));
        mx1 = fmaxf(mx1, __shfl_xor_sync(0xffffffffu, mx1, 1));
        mx1 = fmaxf(mx1, __shfl_xor_sync(0xffffffffu, mx1, 2));
        float mn0 = fmaxf(mr0, mx0), mn1 = fmaxf(mr1, mx1);
        float cr0 = __expf(mr0 - mn0), cr1 = __expf(mr1 - mn1);
        mr0 = mn0; mr1 = mn1;
        float sum0 = 0.0f, sum1 = 0.0f;
#pragma unroll
        for (int nt = 0; nt < 8; nt++) {
            s[nt][0] = __expf(s[nt][0] - mn0); sum0 += s[nt][0];
            s[nt][1] = __expf(s[nt][1] - mn0); sum0 += s[nt][1];
            s[nt][2] = __expf(s[nt][2] - mn1); sum1 += s[nt][2];
            s[nt][3] = __expf(s[nt][3] - mn1); sum1 += s[nt][3];
        }
        sum0 += __shfl_xor_sync(0xffffffffu, sum0, 1);
        sum0 += __shfl_xor_sync(0xffffffffu, sum0, 2);
        sum1 += __shfl_xor_sync(0xffffffffu, sum1, 1);
        sum1 += __shfl_xor_sync(0xffffffffu, sum1, 2);
        lr0 = lr0 * cr0 + sum0;
        lr1 = lr1 * cr1 + sum1;
#pragma unroll
        for (int nt = 0; nt < 8; nt++) {
            o[nt][0] *= cr0; o[nt][1] *= cr0; o[nt][2] *= cr1; o[nt][3] *= cr1;
        }

        // Stage P (pre-converted tf32) to per-warp smem
        const int pr = 16 * w + g;
#pragma unroll
        for (int nt = 0; nt < 8; nt++) {
            *reinterpret_cast<uint2*>(&Pu[pr * PSTR + 8 * nt + 2 * cc]) =
                make_uint2(f2tf(s[nt][0]), f2tf(s[nt][1]));
            *reinterpret_cast<uint2*>(&Pu[(pr + 8) * PSTR + 8 * nt + 2 * cc]) =
                make_uint2(f2tf(s[nt][2]), f2tf(s[nt][3]));
        }
        __syncwarp();

        // O += P @ V
#pragma unroll
        for (int ks = 0; ks < 8; ks++) {
            unsigned af[4];
            af[0] = Pu[pr * PSTR + 8 * ks + cc];
            af[1] = Pu[(pr + 8) * PSTR + 8 * ks + cc];
            af[2] = Pu[pr * PSTR + 8 * ks + cc + 4];
            af[3] = Pu[(pr + 8) * PSTR + 8 * ks + cc + 4];
#pragma unroll
            for (int nt = 0; nt < 8; nt++) {
                unsigned bf[2];
                bf[0] = f2tf(vp[(8 * ks + cc) * VSTR + 8 * nt + g]);
                bf[1] = f2tf(vp[(8 * ks + cc + 4) * VSTR + 8 * nt + g]);
                mma8(o[nt], af, bf);
            }
        }
        __syncthreads();
    }

    // Normalize and write to g_vals[B,S,D], col = h*64 + d
    float inv0 = 1.0f / lr0, inv1 = 1.0f / lr1;
    float* Og = g_vals + ((size_t)blockIdx.z * S_LEN) * D_MODEL + blockIdx.y * HDIM;
#pragma unroll
    for (int nt = 0; nt < 8; nt++) {
        int col = 8 * nt + 2 * cc;
        *reinterpret_cast<float2*>(Og + (size_t)r0 * D_MODEL + col) =
            make_float2(o[nt][0] * inv0, o[nt][1] * inv0);
        *reinterpret_cast<float2*>(Og + (size_t)(r0 + 8) * D_MODEL + col) =
            make_float2(o[nt][2] * inv1, o[nt][3] * inv1);
    }
}

// ---------------------------------------------------------------------------
// Launch
// ---------------------------------------------------------------------------
extern "C" void kernel_launch(void* const* d_in, const int* in_sizes, int n_in,
                              void* d_out, int out_size)
{
    const float* x     = (const float*)d_in[0];
    const float* w_qkv = (const float*)d_in[1];
    const float* b_qkv = (const float*)d_in[2];
    const float* w_o   = (const float*)d_in[3];
    const float* b_o   = (const float*)d_in[4];
    float* out = (float*)d_out;

    const int gemm_smem = 4 * GSZ * (int)sizeof(float);            // 73728
    const int attn_smem = ATTN_SMEM_FLOATS * (int)sizeof(float);   // 106496
    cudaFuncSetAttribute(gemm_qkv_tc, cudaFuncAttributeMaxDynamicSharedMemorySize, gemm_smem);
    cudaFuncSetAttribute(gemm_o_tc,   cudaFuncAttributeMaxDynamicSharedMemorySize, gemm_smem);
    cudaFuncSetAttribute(attn_tc,     cudaFuncAttributeMaxDynamicSharedMemorySize, attn_smem);

    // QKV projection: N=3072 -> 24 tiles, M=4096 -> 32 tiles
    gemm_qkv_tc<<<dim3(24, 32), 256, gemm_smem>>>(x, w_qkv, b_qkv);

    // Attention: 16 q-tiles x 16 heads x 2 batches
    attn_tc<<<dim3(S_LEN / 128, NHEAD, BATCH), 256, attn_smem>>>();

    // Output projection: N=1024 -> 8 tiles, M=4096 -> 32 tiles
    gemm_o_tc<<<dim3(8, 32), 256, gemm_smem>>>(w_o, b_o, out);
}

// round 5
// speedup vs baseline: 6.9781x; 2.0352x over previous
#include <cuda_runtime.h>
#include <cuda_fp16.h>

#define S_LEN   2048
#define D_MODEL 1024
#define NHEAD   16
#define HDIM    64
#define BATCH   2

// Scratch (allocation-free rule: __device__ globals), all fp16
__device__ __half g_xh[(size_t)BATCH * S_LEN * D_MODEL];        // x in fp16
__device__ __half g_wqkvh[(size_t)3 * D_MODEL * D_MODEL];       // w_qkv in fp16
__device__ __half g_woh[(size_t)D_MODEL * D_MODEL];             // w_o in fp16
__device__ __half g_q [(size_t)BATCH * NHEAD * S_LEN * HDIM];   // [b][h][s][d]
__device__ __half g_k [(size_t)BATCH * NHEAD * S_LEN * HDIM];   // [b][h][s][d]
__device__ __half g_vt[(size_t)BATCH * NHEAD * HDIM * S_LEN];   // [b][h][d][s] (transposed!)
__device__ __half g_vals[(size_t)BATCH * S_LEN * D_MODEL];      // attention out

// ---------------------------------------------------------------------------
// Helpers
// ---------------------------------------------------------------------------
__device__ __forceinline__ void mma16(float* d, const unsigned* a, const unsigned* b) {
    asm volatile("mma.sync.aligned.m16n8k16.row.col.f32.f16.f16.f32 "
        "{%0,%1,%2,%3}, {%4,%5,%6,%7}, {%8,%9}, {%0,%1,%2,%3};"
        : "+f"(d[0]), "+f"(d[1]), "+f"(d[2]), "+f"(d[3])
        : "r"(a[0]), "r"(a[1]), "r"(a[2]), "r"(a[3]), "r"(b[0]), "r"(b[1]));
}
__device__ __forceinline__ unsigned pack2(float lo, float hi) {
    __half2 h = __floats2half2_rn(lo, hi);
    return *reinterpret_cast<unsigned*>(&h);
}
__device__ __forceinline__ void cp16(unsigned dst, const void* src) {
    asm volatile("cp.async.cg.shared.global [%0], [%1], 16;" :: "r"(dst), "l"(src) : "memory");
}
#define CP_COMMIT asm volatile("cp.async.commit_group;" ::: "memory")
#define CP_WAIT2  asm volatile("cp.async.wait_group 2;" ::: "memory")
#define CP_WAIT1  asm volatile("cp.async.wait_group 1;" ::: "memory")

// fp32 -> fp16 conversion pass (vectorized, n multiple of 4)
__global__ __launch_bounds__(256) void cvt_fp16(const float* __restrict__ src,
                                                __half* __restrict__ dst)
{
    int idx = blockIdx.x * 256 + threadIdx.x;
    float4 v = reinterpret_cast<const float4*>(src)[idx];
    __half2* d2 = reinterpret_cast<__half2*>(dst) + 2 * idx;
    d2[0] = __floats2half2_rn(v.x, v.y);
    d2[1] = __floats2half2_rn(v.z, v.w);
}

// ---------------------------------------------------------------------------
// fp16 GEMM core: C(128x128) = A(128xK) * B(128xK)^T, m16n8k16.
// 256 threads, 8 warps 2x4, warp tile 64x32, BK=32, 3-stage cp.async.
// smem stride 40 fp16 (80B) -> all LDS.32 fragment loads conflict-free.
// ---------------------------------------------------------------------------
#define HSTR 40
#define HSZ  (128 * HSTR)   // fp16 elems per matrix per stage

__device__ __forceinline__ void gemm_fp16_core(
    const __half* __restrict__ A, const __half* __restrict__ B, int K,
    int m0, int n0, float acc[4][4][4], __half* sm)
{
    __half* As = sm;             // [3][HSZ]
    __half* Bs = sm + 3 * HSZ;   // [3][HSZ]
    unsigned sA = (unsigned)__cvta_generic_to_shared(As);
    unsigned sB = (unsigned)__cvta_generic_to_shared(Bs);
    const int t = threadIdx.x;
    const int lane = t & 31, w = t >> 5;
    const int g = lane >> 2, cc = lane & 3;
    const int wm = w >> 2, wn = w & 3;

#pragma unroll
    for (int mt = 0; mt < 4; mt++)
#pragma unroll
        for (int nt = 0; nt < 4; nt++)
#pragma unroll
            for (int j = 0; j < 4; j++) acc[mt][nt][j] = 0.0f;

    auto issue = [&](int it, int st) {
        int k0 = it * 32;
#pragma unroll
        for (int i = 0; i < 2; i++) {
            int chunk = t + i * 256;          // 0..511 : 128 rows x 4 x 16B
            int row = chunk >> 2, c8 = (chunk & 3) << 3;
            cp16(sA + (unsigned)(st * HSZ + row * HSTR + c8) * 2u,
                 A + (size_t)(m0 + row) * K + k0 + c8);
            cp16(sB + (unsigned)(st * HSZ + row * HSTR + c8) * 2u,
                 B + (size_t)(n0 + row) * K + k0 + c8);
        }
    };

    const int NIT = K / 32;
    issue(0, 0); CP_COMMIT;
    issue(1, 1); CP_COMMIT;
    for (int it = 0; it < NIT; it++) {
        int st = it % 3;
        if (it + 2 < NIT) issue(it + 2, (it + 2) % 3);
        CP_COMMIT;                 // unconditional: keeps group count aligned
        CP_WAIT2;
        __syncthreads();
        const __half* as = As + st * HSZ;
        const __half* bs = Bs + st * HSZ;
#pragma unroll
        for (int kk = 0; kk < 32; kk += 16) {
            unsigned af[4][4], bf[4][2];
#pragma unroll
            for (int mt = 0; mt < 4; mt++) {
                int r = 64 * wm + 16 * mt + g;
                af[mt][0] = *reinterpret_cast<const unsigned*>(as + r * HSTR + kk + 2 * cc);
                af[mt][1] = *reinterpret_cast<const unsigned*>(as + (r + 8) * HSTR + kk + 2 * cc);
                af[mt][2] = *reinterpret_cast<const unsigned*>(as + r * HSTR + kk + 8 + 2 * cc);
                af[mt][3] = *reinterpret_cast<const unsigned*>(as + (r + 8) * HSTR + kk + 8 + 2 * cc);
            }
#pragma unroll
            for (int nt = 0; nt < 4; nt++) {
                int col = 32 * wn + 8 * nt + g;
                bf[nt][0] = *reinterpret_cast<const unsigned*>(bs + col * HSTR + kk + 2 * cc);
                bf[nt][1] = *reinterpret_cast<const unsigned*>(bs + col * HSTR + kk + 8 + 2 * cc);
            }
#pragma unroll
            for (int mt = 0; mt < 4; mt++)
#pragma unroll
                for (int nt = 0; nt < 4; nt++)
                    mma16(acc[mt][nt], af[mt], bf[nt]);
        }
        __syncthreads();
    }
}

// ---------------------------------------------------------------------------
// GEMM 1: qkv = x @ w_qkv^T + b_qkv -> g_q/g_k (row-major) and g_vt (transposed)
// ---------------------------------------------------------------------------
__global__ __launch_bounds__(256, 2) void gemm_qkv_tc(const float* __restrict__ bias)
{
    extern __shared__ __half smh[];
    float acc[4][4][4];
    const int m0 = blockIdx.y * 128, n0 = blockIdx.x * 128;
    gemm_fp16_core(g_xh, g_wqkvh, D_MODEL, m0, n0, acc, smh);

    const int lane = threadIdx.x & 31, w = threadIdx.x >> 5;
    const int g = lane >> 2, cc = lane & 3;
    const int wm = w >> 2, wn = w & 3;
#pragma unroll
    for (int mt = 0; mt < 4; mt++) {
#pragma unroll
        for (int nt = 0; nt < 4; nt++) {
            int n = n0 + 32 * wn + 8 * nt + 2 * cc;
            int h = n / 192;
            int r = n - h * 192;
            int part = r >> 6;
            int d = r & 63;
            float b0 = bias[n], b1 = bias[n + 1];
#pragma unroll
            for (int hi = 0; hi < 2; hi++) {
                int m = m0 + 64 * wm + 16 * mt + g + 8 * hi;
                int bb = m >> 11, s = m & 2047;
                float v0 = acc[mt][nt][2 * hi] + b0;
                float v1 = acc[mt][nt][2 * hi + 1] + b1;
                if (part == 2) {
                    // transposed: g_vt[b][h][d][s]
                    size_t off = (((size_t)bb * NHEAD + h) * HDIM + d) * S_LEN + s;
                    g_vt[off]          = __float2half_rn(v0);
                    g_vt[off + S_LEN]  = __float2half_rn(v1);
                } else {
                    size_t off = (((size_t)bb * NHEAD + h) * S_LEN + s) * HDIM + d;
                    __half2 hv = __floats2half2_rn(v0, v1);
                    *reinterpret_cast<__half2*>((part == 0 ? g_q : g_k) + off) = hv;
                }
            }
        }
    }
}

// ---------------------------------------------------------------------------
// GEMM 2: out = vals @ w_o^T + b_o  (fp32 output)
// ---------------------------------------------------------------------------
__global__ __launch_bounds__(256, 2) void gemm_o_tc(const float* __restrict__ bias,
                                                    float* __restrict__ out)
{
    extern __shared__ __half smh[];
    float acc[4][4][4];
    const int m0 = blockIdx.y * 128, n0 = blockIdx.x * 128;
    gemm_fp16_core(g_vals, g_woh, D_MODEL, m0, n0, acc, smh);

    const int lane = threadIdx.x & 31, w = threadIdx.x >> 5;
    const int g = lane >> 2, cc = lane & 3;
    const int wm = w >> 2, wn = w & 3;
#pragma unroll
    for (int mt = 0; mt < 4; mt++) {
#pragma unroll
        for (int nt = 0; nt < 4; nt++) {
            int n = n0 + 32 * wn + 8 * nt + 2 * cc;
            float b0 = bias[n], b1 = bias[n + 1];
#pragma unroll
            for (int hi = 0; hi < 2; hi++) {
                int m = m0 + 64 * wm + 16 * mt + g + 8 * hi;
                *reinterpret_cast<float2*>(out + (size_t)m * D_MODEL + n) =
                    make_float2(acc[mt][nt][2 * hi] + b0, acc[mt][nt][2 * hi + 1] + b1);
            }
        }
    }
}

// ---------------------------------------------------------------------------
// Flash attention, fp16 m16n8k16. Block = 128 q rows of one (b,h), 8 warps.
// Q frags in regs (pre-scaled 0.125). K [kv][d] and Vt [d][kv] tiles
// double-buffered via cp.async, stride 72 fp16 -> conflict-free LDS.32.
// P C-fragments repack DIRECTLY into A-fragments for P@V (no smem staging).
// ---------------------------------------------------------------------------
#define ASTR 72
#define ATILE (64 * ASTR)                       // fp16 elems per tile per stage
#define ATTN_SMEM_BYTES (2 * 2 * ATILE * 2)     // K+V, 2 stages, fp16 = 36864

__global__ __launch_bounds__(256, 2) void attn_tc()
{
    extern __shared__ __half smh[];
    __half* Ks = smh;                 // [2][64][ASTR]
    __half* Vs = smh + 2 * ATILE;     // [2][64][ASTR]
    unsigned sK = (unsigned)__cvta_generic_to_shared(Ks);
    unsigned sV = (unsigned)__cvta_generic_to_shared(Vs);

    const int t = threadIdx.x, lane = t & 31, w = t >> 5;
    const int g = lane >> 2, cc = lane & 3;
    const int q0 = blockIdx.x * 128;
    const size_t base = ((size_t)blockIdx.z * NHEAD + blockIdx.y) * S_LEN * HDIM;

    // Q fragments (4 ksteps of 16), scaled by 0.125 (exact in fp16)
    unsigned qf[4][4];
    const int r0 = q0 + 16 * w + g;
    {
        const __half* Qg = g_q + base;
        const __half2 sc = __floats2half2_rn(0.125f, 0.125f);
#pragma unroll
        for (int ks = 0; ks < 4; ks++) {
            int c = 16 * ks + 2 * cc;
            __half2 h0 = __hmul2(*reinterpret_cast<const __half2*>(Qg + (size_t)r0 * HDIM + c), sc);
            __half2 h1 = __hmul2(*reinterpret_cast<const __half2*>(Qg + (size_t)(r0 + 8) * HDIM + c), sc);
            __half2 h2 = __hmul2(*reinterpret_cast<const __half2*>(Qg + (size_t)r0 * HDIM + c + 8), sc);
            __half2 h3 = __hmul2(*reinterpret_cast<const __half2*>(Qg + (size_t)(r0 + 8) * HDIM + c + 8), sc);
            qf[ks][0] = *reinterpret_cast<unsigned*>(&h0);
            qf[ks][1] = *reinterpret_cast<unsigned*>(&h1);
            qf[ks][2] = *reinterpret_cast<unsigned*>(&h2);
            qf[ks][3] = *reinterpret_cast<unsigned*>(&h3);
        }
    }

    float o[8][4];
#pragma unroll
    for (int nt = 0; nt < 8; nt++)
#pragma unroll
        for (int j = 0; j < 4; j++) o[nt][j] = 0.0f;
    float mr0 = -1e30f, mr1 = -1e30f, lr0 = 0.0f, lr1 = 0.0f;

    auto issue = [&](int kt, int st) {
        const __half* kg  = g_k  + base + (size_t)kt * 64 * HDIM;   // [kv][d]
        const __half* vtg = g_vt + base;                            // [d][s]
#pragma unroll
        for (int i = 0; i < 2; i++) {
            int chunk = t + i * 256;           // 0..511 : 64 rows x 8 x 16B
            int row = chunk >> 3, c8 = (chunk & 7) << 3;
            cp16(sK + (unsigned)(st * ATILE + row * ASTR + c8) * 2u, kg + row * HDIM + c8);
            cp16(sV + (unsigned)(st * ATILE + row * ASTR + c8) * 2u,
                 vtg + (size_t)row * S_LEN + kt * 64 + c8);
        }
    };

    const int NT = S_LEN / 64;
    issue(0, 0); CP_COMMIT;
    for (int kt = 0; kt < NT; kt++) {
        int st = kt & 1;
        if (kt + 1 < NT) issue(kt + 1, st ^ 1);
        CP_COMMIT;                 // unconditional
        CP_WAIT1;
        __syncthreads();

        const __half* kp = Ks + st * ATILE;
        const __half* vp = Vs + st * ATILE;

        // Scores: S = (Q*0.125) @ K^T  (warp: 16 rows x 64 kv)
        float s[8][4];
#pragma unroll
        for (int nt = 0; nt < 8; nt++)
#pragma unroll
            for (int j = 0; j < 4; j++) s[nt][j] = 0.0f;
#pragma unroll
        for (int ks = 0; ks < 4; ks++) {
#pragma unroll
            for (int nt = 0; nt < 8; nt++) {
                unsigned bf[2];
                const __half* kr = kp + (8 * nt + g) * ASTR + 16 * ks + 2 * cc;
                bf[0] = *reinterpret_cast<const unsigned*>(kr);
                bf[1] = *reinterpret_cast<const unsigned*>(kr + 8);
                mma16(s[nt], qf[ks], bf);
            }
        }

        // Online softmax (rows g and g+8; quad = 4 lanes)
        float mx0 = -1e30f, mx1 = -1e30f;
#pragma unroll
        for (int nt = 0; nt < 8; nt++) {
            mx0 = fmaxf(mx0, fmaxf(s[nt][0], s[nt][1]));
            mx1 = fmaxf(mx1, fmaxf(s[nt][2], s[nt][3]));
        }
        mx0 = fmaxf(mx0, __shfl_xor_sync(0xffffffffu, mx0, 1));
        mx0 = fmaxf(mx0, __shfl_xor_sync(0xffffffffu, mx0, 2));
        mx1 = fmaxf(mx1, __shfl_xor_sync(0xffffffffu, mx1, 1));
        mx1 = fmaxf(mx1, __shfl_xor_sync(0xffffffffu, mx1, 2));
        float mn0 = fmaxf(mr0, mx0), mn1 = fmaxf(mr1, mx1);
        float cr0 = __expf(mr0 - mn0), cr1 = __expf(mr1 - mn1);
        mr0 = mn0; mr1 = mn1;
        float sum0 = 0.0f, sum1 = 0.0f;
#pragma unroll
        for (int nt = 0; nt < 8; nt++) {
            s[nt][0] = __expf(s[nt][0] - mn0); sum0 += s[nt][0];
            s[nt][1] = __expf(s[nt][1] - mn0); sum0 += s[nt][1];
            s[nt][2] = __expf(s[nt][2] - mn1); sum1 += s[nt][2];
            s[nt][3] = __expf(s[nt][3] - mn1); sum1 += s[nt][3];
        }
        sum0 += __shfl_xor_sync(0xffffffffu, sum0, 1);
        sum0 += __shfl_xor_sync(0xffffffffu, sum0, 2);
        sum1 += __shfl_xor_sync(0xffffffffu, sum1, 1);
        sum1 += __shfl_xor_sync(0xffffffffu, sum1, 2);
        lr0 = lr0 * cr0 + sum0;
        lr1 = lr1 * cr1 + sum1;
#pragma unroll
        for (int nt = 0; nt < 8; nt++) {
            o[nt][0] *= cr0; o[nt][1] *= cr0; o[nt][2] *= cr1; o[nt][3] *= cr1;
        }

        // Repack P C-frags directly into A-frags (no smem!), then O += P @ V
#pragma unroll
        for (int ks = 0; ks < 4; ks++) {
            unsigned af[4];
            af[0] = pack2(s[2 * ks][0],     s[2 * ks][1]);
            af[1] = pack2(s[2 * ks][2],     s[2 * ks][3]);
            af[2] = pack2(s[2 * ks + 1][0], s[2 * ks + 1][1]);
            af[3] = pack2(s[2 * ks + 1][2], s[2 * ks + 1][3]);
#pragma unroll
            for (int nt = 0; nt < 8; nt++) {
                unsigned bf[2];
                const __half* vr = vp + (8 * nt + g) * ASTR + 16 * ks + 2 * cc;
                bf[0] = *reinterpret_cast<const unsigned*>(vr);
                bf[1] = *reinterpret_cast<const unsigned*>(vr + 8);
                mma16(o[nt], af, bf);
            }
        }
        __syncthreads();
    }

    // Normalize, write g_vals (fp16) at [b][s][h*64+d]
    float inv0 = 1.0f / lr0, inv1 = 1.0f / lr1;
    __half* Og = g_vals + ((size_t)blockIdx.z * S_LEN) * D_MODEL + blockIdx.y * HDIM;
#pragma unroll
    for (int nt = 0; nt < 8; nt++) {
        int col = 8 * nt + 2 * cc;
        *reinterpret_cast<__half2*>(Og + (size_t)r0 * D_MODEL + col) =
            __floats2half2_rn(o[nt][0] * inv0, o[nt][1] * inv0);
        *reinterpret_cast<__half2*>(Og + (size_t)(r0 + 8) * D_MODEL + col) =
            __floats2half2_rn(o[nt][2] * inv1, o[nt][3] * inv1);
    }
}

// ---------------------------------------------------------------------------
// Launch
// ---------------------------------------------------------------------------
extern "C" void kernel_launch(void* const* d_in, const int* in_sizes, int n_in,
                              void* d_out, int out_size)
{
    const float* x     = (const float*)d_in[0];
    const float* w_qkv = (const float*)d_in[1];
    const float* b_qkv = (const float*)d_in[2];
    const float* w_o   = (const float*)d_in[3];
    const float* b_o   = (const float*)d_in[4];
    float* out = (float*)d_out;

    const int gemm_smem = 6 * HSZ * (int)sizeof(__half);    // 61440
    cudaFuncSetAttribute(gemm_qkv_tc, cudaFuncAttributeMaxDynamicSharedMemorySize, gemm_smem);
    cudaFuncSetAttribute(gemm_o_tc,   cudaFuncAttributeMaxDynamicSharedMemorySize, gemm_smem);

    __half* xh;  cudaGetSymbolAddress((void**)&xh,  g_xh);
    __half* wqh; cudaGetSymbolAddress((void**)&wqh, g_wqkvh);
    __half* woh; cudaGetSymbolAddress((void**)&woh, g_woh);

    // fp32 -> fp16 pre-conversion
    cvt_fp16<<<(BATCH * S_LEN * D_MODEL) / 1024, 256>>>(x, xh);
    cvt_fp16<<<(3 * D_MODEL * D_MODEL) / 1024, 256>>>(w_qkv, wqh);
    cvt_fp16<<<(D_MODEL * D_MODEL) / 1024, 256>>>(w_o, woh);

    // QKV projection: N=3072 -> 24 tiles, M=4096 -> 32 tiles
    gemm_qkv_tc<<<dim3(24, 32), 256, gemm_smem>>>(b_qkv);

    // Attention: 16 q-tiles x 16 heads x 2 batches
    attn_tc<<<dim3(S_LEN / 128, NHEAD, BATCH), 256, ATTN_SMEM_BYTES>>>();

    // Output projection: N=1024 -> 8 tiles, M=4096 -> 32 tiles
    gemm_o_tc<<<dim3(8, 32), 256, gemm_smem>>>(b_o, out);
}